// round 16
// baseline (speedup 1.0000x reference)
#include <cuda_runtime.h>
#include <cuda_bf16.h>
#include <math_constants.h>
#include <cstdint>

// Problem constants
#define NPTS   32768
#define DIM    256
#define NCODE  8192
#define HWSZ   1024
#define ZQ_ELEMS (32*256*32*32)

// Tiling
#define BM 128                 // points per CTA
#define NT 64                  // codes per tile
#define NTILES (NCODE/NT)      // 128
#define MARGIN 8.0f            // covers int8 quantization error (~6 sigma)
#define NSLOT 32               // candidate slots per point

// SMEM layout (bytes)
#define SM_EB    0                 // e int8 tile 4-buffered: 4 x 16384 = 65536
#define SM_EN    65536             // 4 x 64 floats (1024)
#define SM_SE    66560             // 4 x 64 floats (1024)
#define SM_PBD   67584             // 128 uints (512)
#define SM_PCNT  68096             // 128 ints (512)
#define SM_PCD   68608             // 128 x 32 floats (16384)
#define SM_PCK   84992             // 128 x 32 ints (16384)
#define SMEM_TOTAL 101376

__device__ float g_enorm[NCODE];
__device__ float g_se[NCODE];      // per-code quant scale
__device__ float g_sz[NPTS];       // per-point quant scale
__device__ int   g_best_idx[NPTS];
__device__ unsigned int g_flag[NPTS];
__device__ __align__(16) int8_t g_zq8[NPTS * DIM];
__device__ __align__(16) int8_t g_eq8[NCODE * DIM];

// ---------------- PTX helpers (baseline ISA only) ----------------
__device__ __forceinline__ uint32_t smem_u32(const void* p) {
    uint32_t a;
    asm("{ .reg .u64 t; cvta.to.shared.u64 t, %1; cvt.u32.u64 %0, t; }"
        : "=r"(a) : "l"(p));
    return a;
}

__device__ __forceinline__ void cp_async16(uint32_t dst, const void* src) {
    asm volatile("cp.async.cg.shared.global [%0], [%1], 16;"
        :: "r"(dst), "l"(src) : "memory");
}
#define CP_COMMIT() asm volatile("cp.async.commit_group;" ::: "memory")
#define CP_WAIT0()  asm volatile("cp.async.wait_group 0;" ::: "memory")

__device__ __forceinline__ void mma_s8(int* c, const uint32_t* a,
                                       uint32_t b0, uint32_t b1) {
    asm volatile(
        "mma.sync.aligned.m16n8k32.row.col.s32.s8.s8.s32 "
        "{%0,%1,%2,%3}, {%4,%5,%6,%7}, {%8,%9}, {%0,%1,%2,%3};"
        : "+r"(c[0]), "+r"(c[1]), "+r"(c[2]), "+r"(c[3])
        : "r"(a[0]), "r"(a[1]), "r"(a[2]), "r"(a[3]), "r"(b0), "r"(b1));
}

__device__ __forceinline__ void ldsm_x4(uint32_t* r, uint32_t addr) {
    asm volatile("ldmatrix.sync.aligned.m8n8.x4.shared.b16 {%0,%1,%2,%3}, [%4];"
        : "=r"(r[0]), "=r"(r[1]), "=r"(r[2]), "=r"(r[3]) : "r"(addr));
}

// ---- monotonic float<->uint encoding: enc(a) < enc(b) iff a < b ----
__device__ __forceinline__ uint32_t fenc(float f) {
    uint32_t u = __float_as_uint(f);
    return (u & 0x80000000u) ? ~u : (u | 0x80000000u);
}
__device__ __forceinline__ float fdec(uint32_t u) {
    u = (u & 0x80000000u) ? (u ^ 0x80000000u) : ~u;
    return __uint_as_float(u);
}

__device__ __forceinline__ int q8(float v, float inv) {
    int q = __float2int_rn(v * inv);
    return max(-127, min(127, q));
}

// ---------------- Kernel 0: codebook row norms ----------------
__global__ void k_enorm(const float* __restrict__ emb) {
    int warp = (blockIdx.x * blockDim.x + threadIdx.x) >> 5;
    int lane = threadIdx.x & 31;
    if (warp >= NCODE) return;
    const float4* r = reinterpret_cast<const float4*>(emb + (size_t)warp * DIM);
    float4 a = r[lane];
    float4 b = r[lane + 32];
    float s = a.x*a.x + a.y*a.y + a.z*a.z + a.w*a.w
            + b.x*b.x + b.y*b.y + b.z*b.z + b.w*b.w;
    #pragma unroll
    for (int off = 16; off > 0; off >>= 1)
        s += __shfl_xor_sync(0xffffffffu, s, off);
    if (lane == 0) g_enorm[warp] = s;
}

// ---------------- Kernel 0b: e -> int8 with per-code scale ----------------
__global__ void k_eq(const float* __restrict__ emb) {
    int k = (blockIdx.x * blockDim.x + threadIdx.x) >> 5;
    int lane = threadIdx.x & 31;
    if (k >= NCODE) return;
    const float4* r = reinterpret_cast<const float4*>(emb + (size_t)k * DIM);
    float4 a = r[lane];        // dims 4*lane..+3
    float4 b = r[lane + 32];   // dims 128+4*lane..+3
    float m = fmaxf(fmaxf(fabsf(a.x), fabsf(a.y)), fmaxf(fabsf(a.z), fabsf(a.w)));
    m = fmaxf(m, fmaxf(fmaxf(fabsf(b.x), fabsf(b.y)), fmaxf(fabsf(b.z), fabsf(b.w))));
    #pragma unroll
    for (int off = 16; off > 0; off >>= 1)
        m = fmaxf(m, __shfl_xor_sync(0xffffffffu, m, off));
    float dlt = (m > 0.f) ? m * (1.0f / 127.0f) : 1.0f;
    float inv = 1.0f / dlt;
    uint32_t p0 = (uint32_t)(q8(a.x,inv) & 0xFF) | ((uint32_t)(q8(a.y,inv) & 0xFF) << 8)
                | ((uint32_t)(q8(a.z,inv) & 0xFF) << 16) | ((uint32_t)(q8(a.w,inv) & 0xFF) << 24);
    uint32_t p1 = (uint32_t)(q8(b.x,inv) & 0xFF) | ((uint32_t)(q8(b.y,inv) & 0xFF) << 8)
                | ((uint32_t)(q8(b.z,inv) & 0xFF) << 16) | ((uint32_t)(q8(b.w,inv) & 0xFF) << 24);
    *reinterpret_cast<uint32_t*>(g_eq8 + (size_t)k * DIM + lane * 4) = p0;
    *reinterpret_cast<uint32_t*>(g_eq8 + (size_t)k * DIM + 128 + lane * 4) = p1;
    if (lane == 0) g_se[k] = dlt;
}

// ---------------- Kernel 0c: transpose z -> int8 (n-major) with per-point scale ----
__global__ void k_zq(const float* __restrict__ z) {
    __shared__ float s[32][257];
    int bid = blockIdx.x;          // 1024 blocks
    int b   = bid >> 5;
    int hw0 = (bid & 31) * 32;
    const float* zb = z + (size_t)b * DIM * HWSZ;
    int t = threadIdx.x;           // 256
    #pragma unroll
    for (int i = t; i < 32 * 256; i += 256) {
        int c = i >> 5, hw = i & 31;
        s[hw][c] = zb[(size_t)c * HWSZ + hw0 + hw];
    }
    __syncthreads();
    int wrp = t >> 5, lane = t & 31;
    #pragma unroll 1
    for (int pp = 0; pp < 4; ++pp) {
        int hw = wrp * 4 + pp;
        float m = 0.f;
        float v[8];
        #pragma unroll
        for (int j = 0; j < 8; ++j) {
            v[j] = s[hw][lane * 8 + j];
            m = fmaxf(m, fabsf(v[j]));
        }
        #pragma unroll
        for (int off = 16; off > 0; off >>= 1)
            m = fmaxf(m, __shfl_xor_sync(0xffffffffu, m, off));
        float dlt = (m > 0.f) ? m * (1.0f / 127.0f) : 1.0f;
        float inv = 1.0f / dlt;
        int n = b * HWSZ + hw0 + hw;
        uint32_t pk0 = (uint32_t)(q8(v[0],inv) & 0xFF) | ((uint32_t)(q8(v[1],inv) & 0xFF) << 8)
                     | ((uint32_t)(q8(v[2],inv) & 0xFF) << 16) | ((uint32_t)(q8(v[3],inv) & 0xFF) << 24);
        uint32_t pk1 = (uint32_t)(q8(v[4],inv) & 0xFF) | ((uint32_t)(q8(v[5],inv) & 0xFF) << 8)
                     | ((uint32_t)(q8(v[6],inv) & 0xFF) << 16) | ((uint32_t)(q8(v[7],inv) & 0xFF) << 24);
        *reinterpret_cast<uint2*>(g_zq8 + (size_t)n * DIM + lane * 8) = make_uint2(pk0, pk1);
        if (lane == 0) g_sz[n] = dlt;
    }
}

// ---------------- Kernel 1: int8 IMMA GEMM + true-min bound + exact rescore ----------
__global__ void __launch_bounds__(512, 1)
k_vq(const float* __restrict__ z, const float* __restrict__ emb) {
    extern __shared__ char smem[];
    const uint32_t sb = smem_u32(smem);
    const int tid   = threadIdx.x;
    const int w     = tid >> 5;
    const int lane  = tid & 31;
    const int mgrp  = w >> 1;          // 0..7: which 16 point-rows
    const int ngrp  = w & 1;           // 0..1: which 32-code half of the tile
    const int q     = lane >> 2;
    const int e     = lane & 3;
    const int n0    = blockIdx.x * BM;

    float*    en_s  = reinterpret_cast<float*>(smem + SM_EN);
    float*    se_s  = reinterpret_cast<float*>(smem + SM_SE);
    uint32_t* pbd_u = reinterpret_cast<uint32_t*>(smem + SM_PBD);
    int*      pcnt_s= reinterpret_cast<int*>(smem + SM_PCNT);
    float*    pcd_s = reinterpret_cast<float*>(smem + SM_PCD);
    int*      pck_s = reinterpret_cast<int*>(smem + SM_PCK);

    if (tid < BM) { pbd_u[tid] = 0xFFFFFFFFu; pcnt_s[tid] = 0; }

    const int p0 = mgrp * 16 + q;
    const int p1 = p0 + 8;
    const float nsz0 = -2.0f * g_sz[n0 + p0];
    const float nsz1 = -2.0f * g_sz[n0 + p1];

    // ---- Resident A fragments: 16 rows x K=256 int8 (32 regs) ----
    // m16n8k32 A: a0 = row q,   k-bytes 4e..+3 of the k32 group
    //             a1 = row q+8; a2 = row q, k+16; a3 = row q+8, k+16
    uint32_t Aq[32];
    {
        const int8_t* z0 = g_zq8 + (size_t)(n0 + p0) * DIM;
        const int8_t* z1 = g_zq8 + (size_t)(n0 + p1) * DIM;
        #pragma unroll
        for (int g = 0; g < 8; ++g) {
            int c0 = g * 32 + 4 * e;
            Aq[g*4+0] = *reinterpret_cast<const uint32_t*>(z0 + c0);
            Aq[g*4+1] = *reinterpret_cast<const uint32_t*>(z1 + c0);
            Aq[g*4+2] = *reinterpret_cast<const uint32_t*>(z0 + c0 + 16);
            Aq[g*4+3] = *reinterpret_cast<const uint32_t*>(z1 + c0 + 16);
        }
    }

    // ---- B ldmatrix lane constants: 16 rows (codes) x 2 cols(16B = k-halves) ----
    const int nl  = (lane & 7) | ((lane >> 4) << 3);
    const int h   = (lane >> 3) & 1;
    const int nl7 = nl & 7;

    // ---- cp.async prefetch: 512 thr x 2 x 16B = 16KB int8 tile ----
    const int prow = tid >> 3;        // 0..63 (code row)
    const int ps0  = tid & 7;         // seg pair: ps0 and ps0+8 (16 segs of 16B per row)
    const uint32_t psw0 = (uint32_t)((( ps0     ) ^ (prow & 7)) << 4);
    const uint32_t psw1 = (uint32_t)((((ps0 + 8)) ^ (prow & 7)) << 4);
    auto prefetch = [&](int t, int buf) {
        const int8_t* gh = g_eq8 + (size_t)(t * NT + prow) * DIM;
        uint32_t dbase = sb + SM_EB + buf * 16384 + prow * 256;
        cp_async16(dbase + psw0, gh + ps0 * 16);
        cp_async16(dbase + psw1, gh + (ps0 + 8) * 16);
        CP_COMMIT();
    };
    auto load_scales = [&](int t) {
        if (tid < NT) en_s[(t & 3) * NT + tid] = g_enorm[t * NT + tid];
        else if (tid < 2 * NT) se_s[(t & 3) * NT + tid - NT] = g_se[t * NT + tid - NT];
    };

    // ---- per-tile consume (IMMA + distance filter) ----
    auto consume = [&](int t1) {
        int acc[16];
        #pragma unroll
        for (int i = 0; i < 16; ++i) acc[i] = 0;

        const uint32_t ebase = sb + SM_EB + (t1 & 3) * 16384;
        const uint32_t row0 = ebase + (ngrp * 32 + nl) * 256;        // jj=0
        const uint32_t row1 = ebase + (ngrp * 32 + 16 + nl) * 256;   // jj=1
        auto baddr = [&](uint32_t rowa, int g) -> uint32_t {
            return rowa + (uint32_t)(((2 * g + h) ^ nl7) << 4);
        };

        uint32_t B[2][8];
        ldsm_x4(B[0] + 0, baddr(row0, 0));
        ldsm_x4(B[0] + 4, baddr(row1, 0));
        #pragma unroll
        for (int g = 0; g < 8; ++g) {
            if (g + 1 < 8) {
                ldsm_x4(B[(g + 1) & 1] + 0, baddr(row0, g + 1));
                ldsm_x4(B[(g + 1) & 1] + 4, baddr(row1, g + 1));
            }
            const uint32_t* Bk = B[g & 1];
            const uint32_t* A = &Aq[g * 4];
            mma_s8(acc + 0,  A, Bk[0], Bk[1]);   // codes jj0 + 0..7
            mma_s8(acc + 4,  A, Bk[2], Bk[3]);   // codes jj0 + 8..15
            mma_s8(acc + 8,  A, Bk[4], Bk[5]);   // codes jj1 + 0..7
            mma_s8(acc + 12, A, Bk[6], Bk[7]);   // codes jj1 + 8..15
        }

        // ---- convert acc -> approx distances ----
        const float* enb = en_s + (t1 & 3) * NT;
        const float* seb = se_s + (t1 & 3) * NT;
        float dd[16];
        #pragma unroll
        for (int jt = 0; jt < 4; ++jt) {
            int cl = ngrp * 32 + (jt >> 1) * 16 + (jt & 1) * 8 + 2 * e;
            float2 en2 = *reinterpret_cast<const float2*>(enb + cl);
            float2 se2 = *reinterpret_cast<const float2*>(seb + cl);
            dd[jt*4+0] = fmaf(nsz0 * se2.x, (float)acc[jt*4+0], en2.x);
            dd[jt*4+1] = fmaf(nsz0 * se2.y, (float)acc[jt*4+1], en2.y);
            dd[jt*4+2] = fmaf(nsz1 * se2.x, (float)acc[jt*4+2], en2.x);
            dd[jt*4+3] = fmaf(nsz1 * se2.y, (float)acc[jt*4+3], en2.y);
        }
        float m0 = fminf(fminf(fminf(dd[0], dd[1]), fminf(dd[4], dd[5])),
                         fminf(fminf(dd[8], dd[9]), fminf(dd[12], dd[13])));
        float m1 = fminf(fminf(fminf(dd[2], dd[3]), fminf(dd[6], dd[7])),
                         fminf(fminf(dd[10], dd[11]), fminf(dd[14], dd[15])));
        uint32_t e0 = fenc(m0), e1 = fenc(m1);

        if (t1 == 0) {   // seed TRUE min of tile 0 before any recording
            atomicMin(&pbd_u[p0], e0);
            atomicMin(&pbd_u[p1], e1);
            __syncthreads();
        }

        float b0 = fdec(pbd_u[p0]) + MARGIN;
        float b1 = fdec(pbd_u[p1]) + MARGIN;
        if (m0 < b0 || m1 < b1) {   // rare
            #pragma unroll
            for (int jt = 0; jt < 4; ++jt) {
                int k0 = t1 * NT + ngrp * 32 + (jt >> 1) * 16 + (jt & 1) * 8 + 2 * e;
                const float* a = dd + jt * 4;
                if (a[0] < b0) {
                    int s = atomicAdd(&pcnt_s[p0], 1);
                    if (s < NSLOT) { pcd_s[p0*NSLOT+s] = a[0]; pck_s[p0*NSLOT+s] = k0; }
                }
                if (a[1] < b0) {
                    int s = atomicAdd(&pcnt_s[p0], 1);
                    if (s < NSLOT) { pcd_s[p0*NSLOT+s] = a[1]; pck_s[p0*NSLOT+s] = k0+1; }
                }
                if (a[2] < b1) {
                    int s = atomicAdd(&pcnt_s[p1], 1);
                    if (s < NSLOT) { pcd_s[p1*NSLOT+s] = a[2]; pck_s[p1*NSLOT+s] = k0; }
                }
                if (a[3] < b1) {
                    int s = atomicAdd(&pcnt_s[p1], 1);
                    if (s < NSLOT) { pcd_s[p1*NSLOT+s] = a[3]; pck_s[p1*NSLOT+s] = k0+1; }
                }
            }
        }
        if (t1 > 0) {
            if (e0 < pbd_u[p0]) atomicMin(&pbd_u[p0], e0);
            if (e1 < pbd_u[p1]) atomicMin(&pbd_u[p1], e1);
        }
    };

    // ---- 4-stage pipeline, barrier every 2 tiles (R13-proven ordering) ----
    prefetch(0, 0);
    prefetch(1, 1);
    load_scales(0);
    load_scales(1);

    #pragma unroll 1
    for (int t1 = 0; t1 < NTILES; t1 += 2) {
        CP_WAIT0();          // tiles t1, t1+1 data arrived
        __syncthreads();     // visibility + ALL warps done with tiles t1-2, t1-1
                             // => buffers (t1+2)%4, (t1+3)%4 free to overwrite
        if (t1 + 2 < NTILES) {
            prefetch(t1 + 2, (t1 + 2) & 3);
            prefetch(t1 + 3, (t1 + 3) & 3);
            load_scales(t1 + 2);
            load_scales(t1 + 3);
        }
        consume(t1);
        consume(t1 + 1);
    }

    // ---- exact fp32 rescore of recorded candidates ----
    __syncthreads();
    if (tid < BM) {
        int p = tid;
        int n = n0 + p;
        int cnt = pcnt_s[p];
        int ov = (cnt > NSLOT);
        int lim = ov ? NSLOT : cnt;
        float bound = fdec(pbd_u[p]) + MARGIN;
        const float* zr = z + (size_t)(n >> 10) * (DIM * HWSZ) + (n & 1023);
        float bestd = CUDART_INF_F; int bestk = 0x7fffffff;
        #pragma unroll 1
        for (int j = 0; j < lim; ++j) {
            float dv = pcd_s[p * NSLOT + j];
            if (!(dv < bound)) continue;
            int kv = pck_s[p * NSLOT + j];
            const float* er = emb + (size_t)kv * DIM;
            float dot = 0.f;
            #pragma unroll 8
            for (int c = 0; c < DIM; ++c)
                dot = fmaf(zr[(size_t)c * HWSZ], er[c], dot);
            float dd2 = fmaf(-2.0f, dot, g_enorm[kv]);
            if (dd2 < bestd || (dd2 == bestd && kv < bestk)) { bestd = dd2; bestk = kv; }
        }
        g_best_idx[n] = bestk;
        g_flag[n] = (unsigned)ov;
    }
}

// ---------------- Kernel 1b: exact full-scan fallback for overflowed points ----------------
__global__ void k_fb(const float* __restrict__ z, const float* __restrict__ emb) {
    int w = (blockIdx.x * blockDim.x + threadIdx.x) >> 5;
    int lane = threadIdx.x & 31;
    if (w >= NPTS) return;
    if (g_flag[w] == 0) return;
    const float* zr = z + (size_t)(w >> 10) * (DIM * HWSZ) + (w & 1023);
    float bd = CUDART_INF_F; int bk = 0x7fffffff;
    for (int k = lane; k < NCODE; k += 32) {
        const float* er = emb + (size_t)k * DIM;
        float dot = 0.f;
        #pragma unroll 8
        for (int c = 0; c < DIM; ++c)
            dot = fmaf(zr[(size_t)c * HWSZ], er[c], dot);
        float dd = fmaf(-2.0f, dot, g_enorm[k]);
        if (dd < bd || (dd == bd && k < bk)) { bd = dd; bk = k; }
    }
    #pragma unroll
    for (int off = 16; off > 0; off >>= 1) {
        float od = __shfl_xor_sync(0xffffffffu, bd, off);
        int   ok = __shfl_xor_sync(0xffffffffu, bk, off);
        if (od < bd || (od == bd && ok < bk)) { bd = od; bk = ok; }
    }
    if (lane == 0) g_best_idx[w] = bk;
}

// ---------------- Kernel 2: output writer ----------------
__global__ void k_write(const float* __restrict__ z, const float* __restrict__ emb,
                        float* __restrict__ out, int out_size) {
    int i = blockIdx.x * 256 + threadIdx.x;
    if (i >= out_size) return;
    if (i < ZQ_ELEMS) {
        int hw = i & 1023;
        int bc = i >> 10;
        int c  = bc & 255;
        int b  = bc >> 8;
        int n  = (b << 10) + hw;
        int k  = g_best_idx[n];
        float ev = emb[(size_t)k * DIM + c];
        float zv = z[i];
        out[i] = __fadd_rn(zv, __fsub_rn(ev, zv));
    } else {
        int j = i - ZQ_ELEMS;
        out[i] = (j < NPTS) ? (float)g_best_idx[j] : 0.0f;
    }
}

extern "C" void kernel_launch(void* const* d_in, const int* in_sizes, int n_in,
                              void* d_out, int out_size) {
    const float* z   = (const float*)d_in[0];
    const float* emb = (const float*)d_in[1];
    if (in_sizes[0] != ZQ_ELEMS) {
        const float* tmp = z; z = emb; emb = tmp;
    }
    float* out = (float*)d_out;

    cudaFuncSetAttribute(k_vq, cudaFuncAttributeMaxDynamicSharedMemorySize,
                         SMEM_TOTAL);

    k_enorm<<<NCODE / 8, 256>>>(emb);
    k_eq<<<NCODE / 8, 256>>>(emb);
    k_zq<<<1024, 256>>>(z);
    k_vq<<<NPTS / BM, 512, SMEM_TOTAL>>>(z, emb);
    k_fb<<<NPTS / 8, 256>>>(z, emb);
    int wgrid = (out_size + 255) / 256;
    k_write<<<wgrid, 256>>>(z, emb, out, out_size);
}

// round 17
// speedup vs baseline: 1.1385x; 1.1385x over previous
#include <cuda_runtime.h>
#include <cuda_bf16.h>
#include <math_constants.h>
#include <cstdint>

// Problem constants
#define NPTS   32768
#define DIM    256
#define NCODE  8192
#define HWSZ   1024
#define ZQ_ELEMS (32*256*32*32)

// Tiling
#define BM 128                 // points per CTA
#define NT 64                  // codes per tile
#define NTILES (NCODE/NT)      // 128
#define MARGIN 8.0f            // ~5 sigma of fp8 distance error
#define NSLOT 32               // candidate slots per point

// SMEM layout (bytes)
#define SM_EB    0                 // e fp8 tile 4-buffered: 4 x 16384 = 65536
#define SM_EN    65536             // 4 x 64 floats (1024)
#define SM_PBD   66560             // 128 uints (512)
#define SM_PCNT  67072             // 128 ints (512)
#define SM_PCD   67584             // 128 x 32 floats (16384)
#define SM_PCK   83968             // 128 x 32 ints (16384)
#define SMEM_TOTAL 100352

__device__ float g_enorm[NCODE];
__device__ int   g_best_idx[NPTS];
__device__ unsigned int g_flag[NPTS];
__device__ __align__(16) uint8_t g_zq8[NPTS * DIM];   // z as e4m3, n-major
__device__ __align__(16) uint8_t g_eq8[NCODE * DIM];  // e as e4m3

// ---------------- PTX helpers (baseline ISA only) ----------------
__device__ __forceinline__ uint32_t smem_u32(const void* p) {
    uint32_t a;
    asm("{ .reg .u64 t; cvta.to.shared.u64 t, %1; cvt.u32.u64 %0, t; }"
        : "=r"(a) : "l"(p));
    return a;
}

__device__ __forceinline__ void cp_async16(uint32_t dst, const void* src) {
    asm volatile("cp.async.cg.shared.global [%0], [%1], 16;"
        :: "r"(dst), "l"(src) : "memory");
}
#define CP_COMMIT() asm volatile("cp.async.commit_group;" ::: "memory")
#define CP_WAIT0()  asm volatile("cp.async.wait_group 0;" ::: "memory")

// FP8 e4m3 MMA, f32 accumulate (baseline PTX, sm_89+)
__device__ __forceinline__ void mma_e4m3(float* c, const uint32_t* a,
                                         uint32_t b0, uint32_t b1) {
    asm volatile(
        "mma.sync.aligned.m16n8k32.row.col.f32.e4m3.e4m3.f32 "
        "{%0,%1,%2,%3}, {%4,%5,%6,%7}, {%8,%9}, {%0,%1,%2,%3};"
        : "+f"(c[0]), "+f"(c[1]), "+f"(c[2]), "+f"(c[3])
        : "r"(a[0]), "r"(a[1]), "r"(a[2]), "r"(a[3]), "r"(b0), "r"(b1));
}

__device__ __forceinline__ void ldsm_x4(uint32_t* r, uint32_t addr) {
    asm volatile("ldmatrix.sync.aligned.m8n8.x4.shared.b16 {%0,%1,%2,%3}, [%4];"
        : "=r"(r[0]), "=r"(r[1]), "=r"(r[2]), "=r"(r[3]) : "r"(addr));
}

// pack 4 floats (v0..v3, ascending byte order) into 4 e4m3 bytes
__device__ __forceinline__ uint32_t fp8x4(float v0, float v1, float v2, float v3) {
    uint16_t lo, hi;
    asm("cvt.rn.satfinite.e4m3x2.f32 %0, %1, %2;" : "=h"(lo) : "f"(v1), "f"(v0));
    asm("cvt.rn.satfinite.e4m3x2.f32 %0, %1, %2;" : "=h"(hi) : "f"(v3), "f"(v2));
    return (uint32_t)lo | ((uint32_t)hi << 16);
}

// ---- monotonic float<->uint encoding: enc(a) < enc(b) iff a < b ----
__device__ __forceinline__ uint32_t fenc(float f) {
    uint32_t u = __float_as_uint(f);
    return (u & 0x80000000u) ? ~u : (u | 0x80000000u);
}
__device__ __forceinline__ float fdec(uint32_t u) {
    u = (u & 0x80000000u) ? (u ^ 0x80000000u) : ~u;
    return __uint_as_float(u);
}

// ---------------- Kernel 0: codebook row norms ----------------
__global__ void k_enorm(const float* __restrict__ emb) {
    int warp = (blockIdx.x * blockDim.x + threadIdx.x) >> 5;
    int lane = threadIdx.x & 31;
    if (warp >= NCODE) return;
    const float4* r = reinterpret_cast<const float4*>(emb + (size_t)warp * DIM);
    float4 a = r[lane];
    float4 b = r[lane + 32];
    float s = a.x*a.x + a.y*a.y + a.z*a.z + a.w*a.w
            + b.x*b.x + b.y*b.y + b.z*b.z + b.w*b.w;
    #pragma unroll
    for (int off = 16; off > 0; off >>= 1)
        s += __shfl_xor_sync(0xffffffffu, s, off);
    if (lane == 0) g_enorm[warp] = s;
}

// ---------------- Kernel 0b: e -> e4m3 ----------------
__global__ void k_eq(const float* __restrict__ emb) {
    int k = (blockIdx.x * blockDim.x + threadIdx.x) >> 5;
    int lane = threadIdx.x & 31;
    if (k >= NCODE) return;
    const float4* r = reinterpret_cast<const float4*>(emb + (size_t)k * DIM);
    float4 a = r[lane];        // dims 4*lane..+3
    float4 b = r[lane + 32];   // dims 128+4*lane..+3
    *reinterpret_cast<uint32_t*>(g_eq8 + (size_t)k * DIM + lane * 4) =
        fp8x4(a.x, a.y, a.z, a.w);
    *reinterpret_cast<uint32_t*>(g_eq8 + (size_t)k * DIM + 128 + lane * 4) =
        fp8x4(b.x, b.y, b.z, b.w);
}

// ---------------- Kernel 0c: transpose z -> e4m3 (n-major) ----------------
__global__ void k_zq(const float* __restrict__ z) {
    __shared__ float s[32][257];
    int bid = blockIdx.x;          // 1024 blocks
    int b   = bid >> 5;
    int hw0 = (bid & 31) * 32;
    const float* zb = z + (size_t)b * DIM * HWSZ;
    int t = threadIdx.x;           // 256
    #pragma unroll
    for (int i = t; i < 32 * 256; i += 256) {
        int c = i >> 5, hw = i & 31;
        s[hw][c] = zb[(size_t)c * HWSZ + hw0 + hw];
    }
    __syncthreads();
    int wrp = t >> 5, lane = t & 31;
    #pragma unroll 1
    for (int pp = 0; pp < 4; ++pp) {
        int hw = wrp * 4 + pp;
        int n = b * HWSZ + hw0 + hw;
        float v[8];
        #pragma unroll
        for (int j = 0; j < 8; ++j) v[j] = s[hw][lane * 8 + j];
        uint32_t pk0 = fp8x4(v[0], v[1], v[2], v[3]);
        uint32_t pk1 = fp8x4(v[4], v[5], v[6], v[7]);
        *reinterpret_cast<uint2*>(g_zq8 + (size_t)n * DIM + lane * 8) =
            make_uint2(pk0, pk1);
    }
}

// ---------------- Kernel 1: FP8 QMMA GEMM + true-min bound + exact rescore ----------
__global__ void __launch_bounds__(512, 1)
k_vq(const float* __restrict__ z, const float* __restrict__ emb) {
    extern __shared__ char smem[];
    const uint32_t sb = smem_u32(smem);
    const int tid   = threadIdx.x;
    const int w     = tid >> 5;
    const int lane  = tid & 31;
    const int mgrp  = w >> 1;          // 0..7: which 16 point-rows
    const int ngrp  = w & 1;           // 0..1: which 32-code half of the tile
    const int q     = lane >> 2;
    const int e     = lane & 3;
    const int n0    = blockIdx.x * BM;

    float*    en_s  = reinterpret_cast<float*>(smem + SM_EN);
    uint32_t* pbd_u = reinterpret_cast<uint32_t*>(smem + SM_PBD);
    int*      pcnt_s= reinterpret_cast<int*>(smem + SM_PCNT);
    float*    pcd_s = reinterpret_cast<float*>(smem + SM_PCD);
    int*      pck_s = reinterpret_cast<int*>(smem + SM_PCK);

    if (tid < BM) { pbd_u[tid] = 0xFFFFFFFFu; pcnt_s[tid] = 0; }

    const int p0 = mgrp * 16 + q;
    const int p1 = p0 + 8;

    // ---- Resident A fragments: 16 rows x K=256 fp8 (32 regs) ----
    // m16n8k32 A: a0 = row q, k-bytes 4e..; a1 = row q+8; a2 = +16; a3 = row q+8,+16
    uint32_t Aq[32];
    {
        const uint8_t* z0 = g_zq8 + (size_t)(n0 + p0) * DIM;
        const uint8_t* z1 = g_zq8 + (size_t)(n0 + p1) * DIM;
        #pragma unroll
        for (int g = 0; g < 8; ++g) {
            int c0 = g * 32 + 4 * e;
            Aq[g*4+0] = *reinterpret_cast<const uint32_t*>(z0 + c0);
            Aq[g*4+1] = *reinterpret_cast<const uint32_t*>(z1 + c0);
            Aq[g*4+2] = *reinterpret_cast<const uint32_t*>(z0 + c0 + 16);
            Aq[g*4+3] = *reinterpret_cast<const uint32_t*>(z1 + c0 + 16);
        }
    }

    // ---- B ldmatrix lane constants ----
    const int nl  = (lane & 7) | ((lane >> 4) << 3);
    const int h   = (lane >> 3) & 1;
    const int nl7 = nl & 7;

    // ---- cp.async prefetch: 512 thr x 2 x 16B = 16KB fp8 tile ----
    const int prow = tid >> 3;        // 0..63 (code row)
    const int ps0  = tid & 7;         // seg pair: ps0 and ps0+8
    const uint32_t psw0 = (uint32_t)((( ps0     ) ^ (prow & 7)) << 4);
    const uint32_t psw1 = (uint32_t)((((ps0 + 8)) ^ (prow & 7)) << 4);
    auto prefetch = [&](int t, int buf) {
        const uint8_t* gh = g_eq8 + (size_t)(t * NT + prow) * DIM;
        uint32_t dbase = sb + SM_EB + buf * 16384 + prow * 256;
        cp_async16(dbase + psw0, gh + ps0 * 16);
        cp_async16(dbase + psw1, gh + (ps0 + 8) * 16);
        CP_COMMIT();
    };
    auto load_en = [&](int t) {
        if (tid < NT) en_s[(t & 3) * NT + tid] = g_enorm[t * NT + tid];
    };

    // ---- per-tile consume (QMMA + distance filter) ----
    auto consume = [&](int t1) {
        float acc[16];
        #pragma unroll
        for (int i = 0; i < 16; ++i) acc[i] = 0.f;

        const uint32_t ebase = sb + SM_EB + (t1 & 3) * 16384;
        const uint32_t row0 = ebase + (ngrp * 32 + nl) * 256;        // jj=0
        const uint32_t row1 = ebase + (ngrp * 32 + 16 + nl) * 256;   // jj=1
        auto baddr = [&](uint32_t rowa, int g) -> uint32_t {
            return rowa + (uint32_t)(((2 * g + h) ^ nl7) << 4);
        };

        uint32_t B[2][8];
        ldsm_x4(B[0] + 0, baddr(row0, 0));
        ldsm_x4(B[0] + 4, baddr(row1, 0));
        #pragma unroll
        for (int g = 0; g < 8; ++g) {
            if (g + 1 < 8) {
                ldsm_x4(B[(g + 1) & 1] + 0, baddr(row0, g + 1));
                ldsm_x4(B[(g + 1) & 1] + 4, baddr(row1, g + 1));
            }
            const uint32_t* Bk = B[g & 1];
            const uint32_t* A = &Aq[g * 4];
            mma_e4m3(acc + 0,  A, Bk[0], Bk[1]);   // codes jj0 + 0..7
            mma_e4m3(acc + 4,  A, Bk[2], Bk[3]);   // codes jj0 + 8..15
            mma_e4m3(acc + 8,  A, Bk[4], Bk[5]);   // codes jj1 + 0..7
            mma_e4m3(acc + 12, A, Bk[6], Bk[7]);   // codes jj1 + 8..15
        }

        // ---- convert acc -> approx distances ----
        const float* enb = en_s + (t1 & 3) * NT;
        float dd[16];
        #pragma unroll
        for (int jt = 0; jt < 4; ++jt) {
            int cl = ngrp * 32 + (jt >> 1) * 16 + (jt & 1) * 8 + 2 * e;
            float2 en2 = *reinterpret_cast<const float2*>(enb + cl);
            dd[jt*4+0] = fmaf(-2.0f, acc[jt*4+0], en2.x);
            dd[jt*4+1] = fmaf(-2.0f, acc[jt*4+1], en2.y);
            dd[jt*4+2] = fmaf(-2.0f, acc[jt*4+2], en2.x);
            dd[jt*4+3] = fmaf(-2.0f, acc[jt*4+3], en2.y);
        }
        float m0 = fminf(fminf(fminf(dd[0], dd[1]), fminf(dd[4], dd[5])),
                         fminf(fminf(dd[8], dd[9]), fminf(dd[12], dd[13])));
        float m1 = fminf(fminf(fminf(dd[2], dd[3]), fminf(dd[6], dd[7])),
                         fminf(fminf(dd[10], dd[11]), fminf(dd[14], dd[15])));
        uint32_t e0 = fenc(m0), e1 = fenc(m1);

        if (t1 == 0) {   // seed TRUE min of tile 0 before any recording
            atomicMin(&pbd_u[p0], e0);
            atomicMin(&pbd_u[p1], e1);
            __syncthreads();
        }

        float b0 = fdec(pbd_u[p0]) + MARGIN;
        float b1 = fdec(pbd_u[p1]) + MARGIN;
        if (m0 < b0 || m1 < b1) {   // rare
            #pragma unroll
            for (int jt = 0; jt < 4; ++jt) {
                int k0 = t1 * NT + ngrp * 32 + (jt >> 1) * 16 + (jt & 1) * 8 + 2 * e;
                const float* a = dd + jt * 4;
                if (a[0] < b0) {
                    int s = atomicAdd(&pcnt_s[p0], 1);
                    if (s < NSLOT) { pcd_s[p0*NSLOT+s] = a[0]; pck_s[p0*NSLOT+s] = k0; }
                }
                if (a[1] < b0) {
                    int s = atomicAdd(&pcnt_s[p0], 1);
                    if (s < NSLOT) { pcd_s[p0*NSLOT+s] = a[1]; pck_s[p0*NSLOT+s] = k0+1; }
                }
                if (a[2] < b1) {
                    int s = atomicAdd(&pcnt_s[p1], 1);
                    if (s < NSLOT) { pcd_s[p1*NSLOT+s] = a[2]; pck_s[p1*NSLOT+s] = k0; }
                }
                if (a[3] < b1) {
                    int s = atomicAdd(&pcnt_s[p1], 1);
                    if (s < NSLOT) { pcd_s[p1*NSLOT+s] = a[3]; pck_s[p1*NSLOT+s] = k0+1; }
                }
            }
        }
        if (t1 > 0) {
            if (e0 < pbd_u[p0]) atomicMin(&pbd_u[p0], e0);
            if (e1 < pbd_u[p1]) atomicMin(&pbd_u[p1], e1);
        }
    };

    // ---- 4-stage pipeline, barrier every 2 tiles (R13-proven ordering) ----
    prefetch(0, 0);
    prefetch(1, 1);
    load_en(0);
    load_en(1);

    #pragma unroll 1
    for (int t1 = 0; t1 < NTILES; t1 += 2) {
        CP_WAIT0();          // tiles t1, t1+1 data arrived
        __syncthreads();     // visibility + ALL warps done with tiles t1-2, t1-1
                             // => buffers (t1+2)%4, (t1+3)%4 free to overwrite
        if (t1 + 2 < NTILES) {
            prefetch(t1 + 2, (t1 + 2) & 3);
            prefetch(t1 + 3, (t1 + 3) & 3);
            load_en(t1 + 2);
            load_en(t1 + 3);
        }
        consume(t1);
        consume(t1 + 1);
    }

    // ---- exact fp32 rescore of recorded candidates ----
    __syncthreads();
    if (tid < BM) {
        int p = tid;
        int n = n0 + p;
        int cnt = pcnt_s[p];
        int ov = (cnt > NSLOT);
        int lim = ov ? NSLOT : cnt;
        float bound = fdec(pbd_u[p]) + MARGIN;
        const float* zr = z + (size_t)(n >> 10) * (DIM * HWSZ) + (n & 1023);
        float bestd = CUDART_INF_F; int bestk = 0x7fffffff;
        #pragma unroll 1
        for (int j = 0; j < lim; ++j) {
            float dv = pcd_s[p * NSLOT + j];
            if (!(dv < bound)) continue;
            int kv = pck_s[p * NSLOT + j];
            const float* er = emb + (size_t)kv * DIM;
            float dot = 0.f;
            #pragma unroll 8
            for (int c = 0; c < DIM; ++c)
                dot = fmaf(zr[(size_t)c * HWSZ], er[c], dot);
            float dd2 = fmaf(-2.0f, dot, g_enorm[kv]);
            if (dd2 < bestd || (dd2 == bestd && kv < bestk)) { bestd = dd2; bestk = kv; }
        }
        g_best_idx[n] = bestk;
        g_flag[n] = (unsigned)ov;
    }
}

// ---------------- Kernel 1b: exact full-scan fallback for overflowed points ----------------
__global__ void k_fb(const float* __restrict__ z, const float* __restrict__ emb) {
    int w = (blockIdx.x * blockDim.x + threadIdx.x) >> 5;
    int lane = threadIdx.x & 31;
    if (w >= NPTS) return;
    if (g_flag[w] == 0) return;
    const float* zr = z + (size_t)(w >> 10) * (DIM * HWSZ) + (w & 1023);
    float bd = CUDART_INF_F; int bk = 0x7fffffff;
    for (int k = lane; k < NCODE; k += 32) {
        const float* er = emb + (size_t)k * DIM;
        float dot = 0.f;
        #pragma unroll 8
        for (int c = 0; c < DIM; ++c)
            dot = fmaf(zr[(size_t)c * HWSZ], er[c], dot);
        float dd = fmaf(-2.0f, dot, g_enorm[k]);
        if (dd < bd || (dd == bd && k < bk)) { bd = dd; bk = k; }
    }
    #pragma unroll
    for (int off = 16; off > 0; off >>= 1) {
        float od = __shfl_xor_sync(0xffffffffu, bd, off);
        int   ok = __shfl_xor_sync(0xffffffffu, bk, off);
        if (od < bd || (od == bd && ok < bk)) { bd = od; bk = ok; }
    }
    if (lane == 0) g_best_idx[w] = bk;
}

// ---------------- Kernel 2: output writer ----------------
__global__ void k_write(const float* __restrict__ z, const float* __restrict__ emb,
                        float* __restrict__ out, int out_size) {
    int i = blockIdx.x * 256 + threadIdx.x;
    if (i >= out_size) return;
    if (i < ZQ_ELEMS) {
        int hw = i & 1023;
        int bc = i >> 10;
        int c  = bc & 255;
        int b  = bc >> 8;
        int n  = (b << 10) + hw;
        int k  = g_best_idx[n];
        float ev = emb[(size_t)k * DIM + c];
        float zv = z[i];
        out[i] = __fadd_rn(zv, __fsub_rn(ev, zv));
    } else {
        int j = i - ZQ_ELEMS;
        out[i] = (j < NPTS) ? (float)g_best_idx[j] : 0.0f;
    }
}

extern "C" void kernel_launch(void* const* d_in, const int* in_sizes, int n_in,
                              void* d_out, int out_size) {
    const float* z   = (const float*)d_in[0];
    const float* emb = (const float*)d_in[1];
    if (in_sizes[0] != ZQ_ELEMS) {
        const float* tmp = z; z = emb; emb = tmp;
    }
    float* out = (float*)d_out;

    cudaFuncSetAttribute(k_vq, cudaFuncAttributeMaxDynamicSharedMemorySize,
                         SMEM_TOTAL);

    k_enorm<<<NCODE / 8, 256>>>(emb);
    k_eq<<<NCODE / 8, 256>>>(emb);
    k_zq<<<1024, 256>>>(z);
    k_vq<<<NPTS / BM, 512, SMEM_TOTAL>>>(z, emb);
    k_fb<<<NPTS / 8, 256>>>(z, emb);
    int wgrid = (out_size + 255) / 256;
    k_write<<<wgrid, 256>>>(z, emb, out, out_size);
}